// round 1
// baseline (speedup 1.0000x reference)
#include <cuda_runtime.h>
#include <cstddef>

#define NB   4
#define HWD  224
#define CIN  256
#define FOUT 256
#define BCN  16
#define OB   14
#define CC   8     // channel chunk in smem
#define FT   64    // filters per CTA

// 0/1 per (n, by, bx) block
__device__ int g_active[NB * BCN * BCN];

// ---------------------------------------------------------------------------
// Kernel 1: pooled-mask activity per block. One CTA per block, 256 threads,
// each thread loads one mask element of the padded 16x16 window (zeros OOB).
// ---------------------------------------------------------------------------
__global__ void active_kernel(const float* __restrict__ mask) {
    int b = blockIdx.x;                 // 0..1023
    int n = b >> 8, by = (b >> 4) & 15, bx = b & 15;
    int t = threadIdx.x;                // 0..255
    int ty = t >> 4, tx = t & 15;
    int h = by * OB - 1 + ty;
    int w = bx * OB - 1 + tx;
    float v = 0.f;
    if (h >= 0 && h < HWD && w >= 0 && w < HWD)
        v = mask[(n * HWD + h) * HWD + w];
    double d = (double)v;
    #pragma unroll
    for (int o = 16; o > 0; o >>= 1)
        d += __shfl_down_sync(0xffffffffu, d, o);
    __shared__ double sred[8];
    if ((t & 31) == 0) sred[t >> 5] = d;
    __syncthreads();
    if (t == 0) {
        double s = 0.0;
        #pragma unroll
        for (int i = 0; i < 8; ++i) s += sred[i];
        g_active[b] = (s * (1.0 / 256.0) > 0.5) ? 1 : 0;
    }
}

// ---------------------------------------------------------------------------
// Kernel 2: conv per (block, 64-filter tile). 196 threads:
//   thread t -> patch = t>>2 (49 patches, each 2x2 output pixels),
//               fg = t&3 (16 filters each) => 64 fp32 accumulators.
// C processed in chunks of 8 through shared memory.
// ---------------------------------------------------------------------------
__global__ void __launch_bounds__(196, 2)
conv_kernel(const float* __restrict__ in, const float* __restrict__ wgt,
            const float* __restrict__ bias, float* __restrict__ out) {
    int b  = blockIdx.x;                 // block id 0..1023
    int ft = blockIdx.y;                 // f tile 0..3
    int n = b >> 8, by = (b >> 4) & 15, bx = b & 15;
    int t = threadIdx.x;                 // 0..195
    int fbase = ft * FT;

    if (!g_active[b]) {
        // zero-fill this block's 14x14 x 64f region (d_out is poisoned)
        int py = t / OB, px = t % OB;    // 196 threads == 196 pixels
        float4 z = make_float4(0.f, 0.f, 0.f, 0.f);
        float* o = out + (((size_t)n * HWD + by * OB + py) * HWD + bx * OB + px) * FOUT + fbase;
        #pragma unroll
        for (int i = 0; i < 16; ++i) ((float4*)o)[i] = z;
        return;
    }

    __shared__ float s_in[CC][16][16];        // 8 KB
    __shared__ float s_w[9][CC][FT];          // 18 KB

    int patch = t >> 2;                       // 0..48
    int fg    = t & 3;                        // 0..3
    int py0 = (patch / 7) * 2, px0 = (patch % 7) * 2;
    int flocal = fg * 16;

    float acc[4][16];
    #pragma unroll
    for (int a = 0; a < 4; ++a)
        #pragma unroll
        for (int k = 0; k < 16; ++k) acc[a][k] = 0.f;

    int h0 = by * OB - 1;
    int w0 = bx * OB - 1;

    for (int cc = 0; cc < CIN / CC; ++cc) {
        __syncthreads();   // previous chunk's compute done before overwrite
        // ---- load input tile 16x16 x CC (transpose c to leading dim) ----
        for (int i = t; i < 16 * 16 * CC / 4; i += 196) {   // 512 float4
            int pos = i >> 1;            // 0..255
            int q   = i & 1;             // which float4 of the CC=8 channels
            int r = pos >> 4, col = pos & 15;
            int h = h0 + r, w = w0 + col;
            float4 v = make_float4(0.f, 0.f, 0.f, 0.f);
            if (h >= 0 && h < HWD && w >= 0 && w < HWD)
                v = *(const float4*)(in + (((size_t)n * HWD + h) * HWD + w) * CIN + cc * CC + q * 4);
            s_in[q * 4 + 0][r][col] = v.x;
            s_in[q * 4 + 1][r][col] = v.y;
            s_in[q * 4 + 2][r][col] = v.z;
            s_in[q * 4 + 3][r][col] = v.w;
        }
        // ---- load weights 9 x CC x 64 ----
        for (int i = t; i < 9 * CC * FT / 4; i += 196) {    // 1152 float4
            int f4  = i & 15;            // 16 float4 across 64 f
            int rem = i >> 4;            // 0..71
            int c  = rem & (CC - 1);
            int kk = rem >> 3;           // 0..8
            *(float4*)&s_w[kk][c][f4 * 4] =
                *(const float4*)(wgt + ((size_t)(kk * CIN) + cc * CC + c) * FOUT + fbase + f4 * 4);
        }
        __syncthreads();

        // ---- compute ----
        #pragma unroll 1
        for (int c = 0; c < CC; ++c) {
            float v[4][4];
            #pragma unroll
            for (int i = 0; i < 4; ++i)
                #pragma unroll
                for (int j = 0; j < 4; ++j)
                    v[i][j] = s_in[c][py0 + i][px0 + j];
            #pragma unroll
            for (int ky = 0; ky < 3; ++ky)
                #pragma unroll
                for (int kx = 0; kx < 3; ++kx) {
                    const float* wp = &s_w[ky * 3 + kx][c][flocal];
                    #pragma unroll
                    for (int q = 0; q < 4; ++q) {
                        float4 wv = *(const float4*)(wp + q * 4);
                        #pragma unroll
                        for (int pi = 0; pi < 2; ++pi)
                            #pragma unroll
                            for (int pj = 0; pj < 2; ++pj) {
                                float x = v[pi + ky][pj + kx];
                                float* a = acc[pi * 2 + pj] + q * 4;
                                a[0] += x * wv.x;
                                a[1] += x * wv.y;
                                a[2] += x * wv.z;
                                a[3] += x * wv.w;
                            }
                    }
                }
        }
    }

    // ---- epilogue: bias + relu + store ----
    float bq[16];
    #pragma unroll
    for (int q = 0; q < 4; ++q) {
        float4 bb = *(const float4*)(bias + fbase + flocal + q * 4);
        bq[q * 4 + 0] = bb.x; bq[q * 4 + 1] = bb.y;
        bq[q * 4 + 2] = bb.z; bq[q * 4 + 3] = bb.w;
    }
    #pragma unroll
    for (int pi = 0; pi < 2; ++pi)
        #pragma unroll
        for (int pj = 0; pj < 2; ++pj) {
            int Y = by * OB + py0 + pi;
            int X = bx * OB + px0 + pj;
            float* o = out + (((size_t)n * HWD + Y) * HWD + X) * FOUT + fbase + flocal;
            int a = pi * 2 + pj;
            #pragma unroll
            for (int q = 0; q < 4; ++q) {
                float4 r;
                r.x = fmaxf(acc[a][q * 4 + 0] + bq[q * 4 + 0], 0.f);
                r.y = fmaxf(acc[a][q * 4 + 1] + bq[q * 4 + 1], 0.f);
                r.z = fmaxf(acc[a][q * 4 + 2] + bq[q * 4 + 2], 0.f);
                r.w = fmaxf(acc[a][q * 4 + 3] + bq[q * 4 + 3], 0.f);
                *(float4*)(o + q * 4) = r;
            }
        }
}

extern "C" void kernel_launch(void* const* d_in, const int* in_sizes, int n_in,
                              void* d_out, int out_size) {
    (void)in_sizes; (void)n_in; (void)out_size;
    const float* in   = (const float*)d_in[0];   // (4,224,224,256) f32
    const float* mask = (const float*)d_in[1];   // (4,224,224,1)   f32
    const float* wgt  = (const float*)d_in[2];   // (3,3,256,256)   f32
    const float* bias = (const float*)d_in[3];   // (256,)          f32
    float* out = (float*)d_out;                  // (4,224,224,256) f32

    active_kernel<<<NB * BCN * BCN, 256>>>(mask);
    dim3 grid(NB * BCN * BCN, FOUT / FT);
    conv_kernel<<<grid, 196>>>(in, wgt, bias, out);
}

// round 3
// speedup vs baseline: 3.2571x; 3.2571x over previous
#include <cuda_runtime.h>
#include <cuda_bf16.h>
#include <cstdint>
#include <cstddef>

#define HWD  224
#define CIN  256
#define FOUT 256
#define OBS  14
#define KTOT 2304            // 9 taps * 256 c
#define KP   6912            // 3 segments * KTOT
#define NCHUNK 4             // 256 c / 64
#define NITER (NCHUNK * 27)  // 108 (cc, seg, tap) stages, 4 k16-steps each

// smem layout (bytes)
#define WIN_HI 0
#define WIN_LO 32768
#define BOFF   65536         // 2 x 16384 B stage buffers
#define BIASOF 98304
#define SMEM_TOTAL 98816

__device__ int g_active[1024];
__device__ __align__(16) __nv_bfloat16 g_W2[256 * KP];   // [f][seg*2304 + tap*256 + c]

__device__ __forceinline__ uint32_t smem_to_u32(const void* p) {
    uint32_t a;
    asm("{ .reg .u64 t; cvta.to.shared.u64 t, %1; cvt.u32.u64 %0, t; }" : "=r"(a) : "l"(p));
    return a;
}

#define LDSM4(r0, r1, r2, r3, addr) \
    asm volatile("ldmatrix.sync.aligned.m8n8.x4.shared.b16 {%0,%1,%2,%3}, [%4];" \
        : "=r"(r0), "=r"(r1), "=r"(r2), "=r"(r3) : "r"(addr))

#define MMA16816(d, a0, a1, a2, a3, b0, b1) \
    asm volatile("mma.sync.aligned.m16n8k16.row.col.f32.bf16.bf16.f32 " \
        "{%0,%1,%2,%3}, {%4,%5,%6,%7}, {%8,%9}, {%0,%1,%2,%3};" \
        : "+f"((d)[0]), "+f"((d)[1]), "+f"((d)[2]), "+f"((d)[3]) \
        : "r"(a0), "r"(a1), "r"(a2), "r"(a3), "r"(b0), "r"(b1))

// ---------------------------------------------------------------------------
// Kernel 1: block activity
// ---------------------------------------------------------------------------
__global__ void active_kernel(const float* __restrict__ mask) {
    int b = blockIdx.x;
    int nb = b >> 8, by = (b >> 4) & 15, bx = b & 15;
    int t = threadIdx.x;
    int ty = t >> 4, tx = t & 15;
    int h = by * OBS - 1 + ty;
    int w = bx * OBS - 1 + tx;
    float v = 0.f;
    if (h >= 0 && h < HWD && w >= 0 && w < HWD)
        v = mask[(nb * HWD + h) * HWD + w];
    double d = (double)v;
    #pragma unroll
    for (int o = 16; o > 0; o >>= 1)
        d += __shfl_down_sync(0xffffffffu, d, o);
    __shared__ double sred[8];
    if ((t & 31) == 0) sred[t >> 5] = d;
    __syncthreads();
    if (t == 0) {
        double s = 0.0;
        #pragma unroll
        for (int i = 0; i < 8; ++i) s += sred[i];
        g_active[b] = (s * (1.0 / 256.0) > 0.5) ? 1 : 0;
    }
}

// ---------------------------------------------------------------------------
// Kernel 2: weight split + transpose into g_W2[f][seg*KTOT + k]
//   seg0 = W_hi (pairs A_hi), seg1 = W_hi (pairs A_lo), seg2 = W_lo (pairs A_hi)
// ---------------------------------------------------------------------------
__global__ void wprep_kernel(const float* __restrict__ wgt) {
    int idx = blockIdx.x * 256 + threadIdx.x;   // 0 .. 2304*256-1
    int f = idx & 255;
    int k = idx >> 8;
    float w = wgt[(size_t)k * 256 + f];
    __nv_bfloat16 h = __float2bfloat16(w);
    __nv_bfloat16 l = __float2bfloat16(w - __bfloat162float(h));
    size_t base = (size_t)f * KP + k;
    g_W2[base]            = h;
    g_W2[base + KTOT]     = h;
    g_W2[base + 2 * KTOT] = l;
}

// ---------------------------------------------------------------------------
// Kernel 3: per-(active block, 128-filter half) implicit conv GEMM via
// mma.sync bf16. 8 warps x n16 slices, 13 m16 tiles each (196 px padded 208).
// ---------------------------------------------------------------------------
__global__ void __launch_bounds__(256, 1)
conv_mma_kernel(const float* __restrict__ in, const float* __restrict__ bias,
                float* __restrict__ out) {
    int b = blockIdx.x;
    int half = blockIdx.y;
    int nb = b >> 8, by = (b >> 4) & 15, bx = b & 15;
    int tid = threadIdx.x;
    int fbase = half * 128;

    if (!g_active[b]) {
        if (tid < 196) {
            int Y = by * OBS + tid / OBS, X = bx * OBS + tid % OBS;
            float4* o = (float4*)(out + (((size_t)nb * HWD + Y) * HWD + X) * FOUT + fbase);
            float4 z = make_float4(0.f, 0.f, 0.f, 0.f);
            #pragma unroll
            for (int i = 0; i < 32; ++i) o[i] = z;
        }
        return;
    }

    extern __shared__ char smem[];
    uint32_t sbase = smem_to_u32(smem);
    int warp = tid >> 5, lane = tid & 31;

    // bias slice to smem
    if (tid < 32) ((float4*)(smem + BIASOF))[tid] = ((const float4*)(bias + fbase))[tid];

    // per-lane A-row table: ldmatrix row m for each m-tile
    int P0[13];
    {
        int mrow = (lane & 7) + ((lane >> 3) & 1) * 8;
        #pragma unroll
        for (int mt = 0; mt < 13; ++mt) {
            int m = mt * 16 + mrow;
            if (m > 195) m = 195;
            int py = m / 14, px = m - py * 14;
            P0[mt] = (py + 1) * 16 + (px + 1);
        }
    }
    int acgl = (lane >> 4) & 1;                         // A cg parity per lane
    int bn   = warp * 16 + ((lane >> 4) & 1) * 8 + (lane & 7);  // B row per lane
    int bg0  = (lane >> 3) & 1;                         // B cg parity per lane
    uint32_t baddr0 = sbase + BOFF + (uint32_t)bn * 128;

    float acc[13][2][4];
    #pragma unroll
    for (int mt = 0; mt < 13; ++mt)
        #pragma unroll
        for (int t = 0; t < 2; ++t)
            #pragma unroll
            for (int j = 0; j < 4; ++j) acc[mt][t][j] = 0.f;

    const float* inb = in + (size_t)nb * HWD * HWD * CIN;
    int h0 = by * OBS - 1;
    int w0 = bx * OBS - 1;

    // ---- prologue: stage B(0) (cc=0, seg=0, tap=0) ----
    {
        const __nv_bfloat16* wb = g_W2;   // seg0, tap0, c0
        #pragma unroll
        for (int j = 0; j < 4; ++j) {
            int u = tid + j * 256;
            int n = u >> 3, g = u & 7;
            uint4 v = *(const uint4*)(wb + (size_t)(fbase + n) * KP + g * 8);
            *(uint4*)(smem + BOFF + n * 128 + (((g ^ (n & 7))) << 4)) = v;
        }
    }

    for (int i = 0; i < NITER; ++i) {
        int cc = i / 27;
        int r = i - cc * 27;
        int seg = r / 9;
        int tap = r - seg * 9;
        int buf = i & 1;

        if (r == 0) {
            // new channel chunk: load 16x16 window (hi+lo) for 64 channels
            __syncthreads();     // all compute on old window done
            int c0 = cc * 64;
            #pragma unroll
            for (int j = 0; j < 8; ++j) {
                int u = tid + j * 256;       // (pixel, 16B group)
                int p = u >> 3, g = u & 7;
                int y = p >> 4, x = p & 15;
                int gy = h0 + y, gx = w0 + x;
                float v[8];
                #pragma unroll
                for (int e = 0; e < 8; ++e) v[e] = 0.f;
                if ((unsigned)gy < HWD && (unsigned)gx < HWD) {
                    const float* sp = inb + (((size_t)gy * HWD + gx) * CIN) + c0 + g * 8;
                    float4 va = ((const float4*)sp)[0];
                    float4 vb = ((const float4*)sp)[1];
                    v[0] = va.x; v[1] = va.y; v[2] = va.z; v[3] = va.w;
                    v[4] = vb.x; v[5] = vb.y; v[6] = vb.z; v[7] = vb.w;
                }
                union { __nv_bfloat16 bf[8]; uint4 u4; } H, L;
                #pragma unroll
                for (int e = 0; e < 8; ++e) {
                    __nv_bfloat16 hh = __float2bfloat16(v[e]);
                    H.bf[e] = hh;
                    L.bf[e] = __float2bfloat16(v[e] - __bfloat162float(hh));
                }
                uint32_t so = p * 128 + (((g ^ (p & 7))) << 4);
                *(uint4*)(smem + WIN_HI + so) = H.u4;
                *(uint4*)(smem + WIN_LO + so) = L.u4;
            }
        }

        // prefetch next B stage into registers
        uint4 br[4];
        if (i + 1 < NITER) {
            int i2 = i + 1;
            int cc2 = i2 / 27;
            int r2 = i2 - cc2 * 27;
            int seg2 = r2 / 9;
            int tap2 = r2 - seg2 * 9;
            const __nv_bfloat16* wb = g_W2 + seg2 * KTOT + tap2 * 256 + cc2 * 64;
            #pragma unroll
            for (int j = 0; j < 4; ++j) {
                int u = tid + j * 256;
                int n = u >> 3, g = u & 7;
                br[j] = *(const uint4*)(wb + (size_t)(fbase + n) * KP + g * 8);
            }
        }

        __syncthreads();   // window + B(i) stores visible; buf (i+1)&1 free

        // ---- compute this (seg, tap) stage: 4 k16 steps ----
        int dy = tap / 3 - 1, dx = tap - (tap / 3) * 3 - 1;
        int doff = dy * 16 + dx;
        uint32_t winb = sbase + ((seg == 1) ? WIN_LO : WIN_HI);
        uint32_t bbuf = baddr0 + buf * 16384;

        #pragma unroll
        for (int kk = 0; kk < 4; ++kk) {
            int bcg = 2 * kk + bg0;
            uint32_t ba = bbuf + (((bcg ^ (bn & 7))) << 4);
            uint32_t b0, b1, b2, b3;
            LDSM4(b0, b1, b2, b3, ba);
            int acg = 2 * kk + acgl;
            #pragma unroll
            for (int mt = 0; mt < 13; ++mt) {
                int P = P0[mt] + doff;
                uint32_t aa = winb + (uint32_t)P * 128 + (((acg ^ (P & 7))) << 4);
                uint32_t a0, a1, a2, a3;
                LDSM4(a0, a1, a2, a3, aa);
                MMA16816(acc[mt][0], a0, a1, a2, a3, b0, b1);
                MMA16816(acc[mt][1], a0, a1, a2, a3, b2, b3);
            }
        }

        // store prefetched B(i+1)
        if (i + 1 < NITER) {
            uint32_t dst = BOFF + ((i + 1) & 1) * 16384;
            #pragma unroll
            for (int j = 0; j < 4; ++j) {
                int u = tid + j * 256;
                int n = u >> 3, g = u & 7;
                *(uint4*)(smem + dst + n * 128 + (((g ^ (n & 7))) << 4)) = br[j];
            }
        }
    }

    // ---- epilogue: bias + relu + store ----
    const float* sb = (const float*)(smem + BIASOF);
    #pragma unroll
    for (int mt = 0; mt < 13; ++mt) {
        #pragma unroll
        for (int t = 0; t < 2; ++t) {
            int nn = warp * 16 + t * 8 + (lane & 3) * 2;
            float bz0 = sb[nn], bz1 = sb[nn + 1];
            #pragma unroll
            for (int h2 = 0; h2 < 2; ++h2) {
                int m = mt * 16 + (lane >> 2) + h2 * 8;
                if (m < 196) {
                    int py = m / 14, px = m - py * 14;
                    float* o = out + (((size_t)nb * HWD + by * OBS + py) * HWD
                                      + bx * OBS + px) * FOUT + fbase + nn;
                    float2 v;
                    v.x = fmaxf(acc[mt][t][h2 * 2 + 0] + bz0, 0.f);
                    v.y = fmaxf(acc[mt][t][h2 * 2 + 1] + bz1, 0.f);
                    *(float2*)o = v;
                }
            }
        }
    }
}

extern "C" void kernel_launch(void* const* d_in, const int* in_sizes, int n_in,
                              void* d_out, int out_size) {
    (void)in_sizes; (void)n_in; (void)out_size;
    const float* in   = (const float*)d_in[0];   // (4,224,224,256)
    const float* mask = (const float*)d_in[1];   // (4,224,224,1)
    const float* wgt  = (const float*)d_in[2];   // (3,3,256,256)
    const float* bias = (const float*)d_in[3];   // (256,)
    float* out = (float*)d_out;

    cudaFuncSetAttribute(conv_mma_kernel,
                         cudaFuncAttributeMaxDynamicSharedMemorySize, SMEM_TOTAL);
    active_kernel<<<1024, 256>>>(mask);
    wprep_kernel<<<2304, 256>>>(wgt);
    dim3 grid(1024, 2);
    conv_mma_kernel<<<grid, 256, SMEM_TOTAL>>>(in, bias, out);
}

// round 4
// speedup vs baseline: 3.4504x; 1.0593x over previous
#include <cuda_runtime.h>
#include <cuda_bf16.h>
#include <cstdint>
#include <cstddef>

#define HWD  224
#define CIN  256
#define FOUT 256
#define OBS  14
#define KTOT 2304            // 9 taps * 256 c
#define KP   6912            // 3 segments * KTOT
#define NCHUNK 4             // 256 c / 64
#define NITER (NCHUNK * 27)  // 108 (cc, seg, tap) stages, 4 k16-steps each

// smem layout (bytes)
#define WIN_HI 0
#define WIN_LO 32768
#define BOFF   65536         // 2 x 16384 B stage buffers
#define BIASOF 98304
#define SMEM_TOTAL 98816

__device__ int g_active[1024];
__device__ __align__(16) __nv_bfloat16 g_W2[256 * KP];   // [f][seg*2304 + tap*256 + c]

__device__ __forceinline__ uint32_t smem_to_u32(const void* p) {
    uint32_t a;
    asm("{ .reg .u64 t; cvta.to.shared.u64 t, %1; cvt.u32.u64 %0, t; }" : "=r"(a) : "l"(p));
    return a;
}

#define LDSM4(r0, r1, r2, r3, addr) \
    asm volatile("ldmatrix.sync.aligned.m8n8.x4.shared.b16 {%0,%1,%2,%3}, [%4];" \
        : "=r"(r0), "=r"(r1), "=r"(r2), "=r"(r3) : "r"(addr))

#define MMA16816(d, a0, a1, a2, a3, b0, b1) \
    asm volatile("mma.sync.aligned.m16n8k16.row.col.f32.bf16.bf16.f32 " \
        "{%0,%1,%2,%3}, {%4,%5,%6,%7}, {%8,%9}, {%0,%1,%2,%3};" \
        : "+f"((d)[0]), "+f"((d)[1]), "+f"((d)[2]), "+f"((d)[3]) \
        : "r"(a0), "r"(a1), "r"(a2), "r"(a3), "r"(b0), "r"(b1))

// ---------------------------------------------------------------------------
// Kernel 1: block activity
// ---------------------------------------------------------------------------
__global__ void active_kernel(const float* __restrict__ mask) {
    int b = blockIdx.x;
    int nb = b >> 8, by = (b >> 4) & 15, bx = b & 15;
    int t = threadIdx.x;
    int ty = t >> 4, tx = t & 15;
    int h = by * OBS - 1 + ty;
    int w = bx * OBS - 1 + tx;
    float v = 0.f;
    if (h >= 0 && h < HWD && w >= 0 && w < HWD)
        v = mask[(nb * HWD + h) * HWD + w];
    double d = (double)v;
    #pragma unroll
    for (int o = 16; o > 0; o >>= 1)
        d += __shfl_down_sync(0xffffffffu, d, o);
    __shared__ double sred[8];
    if ((t & 31) == 0) sred[t >> 5] = d;
    __syncthreads();
    if (t == 0) {
        double s = 0.0;
        #pragma unroll
        for (int i = 0; i < 8; ++i) s += sred[i];
        g_active[b] = (s * (1.0 / 256.0) > 0.5) ? 1 : 0;
    }
}

// ---------------------------------------------------------------------------
// Kernel 2: weight split + transpose into g_W2[f][seg*KTOT + k]
//   seg0 = W_hi (pairs A_hi), seg1 = W_hi (pairs A_lo), seg2 = W_lo (pairs A_hi)
// ---------------------------------------------------------------------------
__global__ void wprep_kernel(const float* __restrict__ wgt) {
    int idx = blockIdx.x * 256 + threadIdx.x;   // 0 .. 2304*256-1
    int f = idx & 255;
    int k = idx >> 8;
    float w = wgt[(size_t)k * 256 + f];
    __nv_bfloat16 h = __float2bfloat16(w);
    __nv_bfloat16 l = __float2bfloat16(w - __bfloat162float(h));
    size_t base = (size_t)f * KP + k;
    g_W2[base]            = h;
    g_W2[base + KTOT]     = h;
    g_W2[base + 2 * KTOT] = l;
}

// ---------------------------------------------------------------------------
// Kernel 3: per-(active block, 128-filter half) implicit conv GEMM via
// mma.sync bf16. 8 warps tiled 4(m) x 2(n): each warp n64 x up-to-4 m16 tiles.
// ---------------------------------------------------------------------------
__global__ void __launch_bounds__(256, 1)
conv_mma_kernel(const float* __restrict__ in, const float* __restrict__ bias,
                float* __restrict__ out) {
    int b = blockIdx.x;
    int fhalf = blockIdx.y;
    int nb = b >> 8, by = (b >> 4) & 15, bx = b & 15;
    int tid = threadIdx.x;
    int fbase = fhalf * 128;

    if (!g_active[b]) {
        if (tid < 196) {
            int Y = by * OBS + tid / OBS, X = bx * OBS + tid % OBS;
            float4* o = (float4*)(out + (((size_t)nb * HWD + Y) * HWD + X) * FOUT + fbase);
            float4 z = make_float4(0.f, 0.f, 0.f, 0.f);
            #pragma unroll
            for (int i = 0; i < 32; ++i) o[i] = z;
        }
        return;
    }

    extern __shared__ char smem[];
    uint32_t sbase = smem_to_u32(smem);
    int warp = tid >> 5, lane = tid & 31;
    int wr = warp & 3;          // m row-group
    int wc = warp >> 2;         // n column-group (n64)

    // bias slice to smem
    if (tid < 32) ((float4*)(smem + BIASOF))[tid] = ((const float4*)(bias + fbase))[tid];

    // per-lane A-row table: ldmatrix row for each of this warp's m-tiles
    int P0[4];
    {
        int mrow = (lane & 7) + ((lane >> 3) & 1) * 8;
        #pragma unroll
        for (int j = 0; j < 4; ++j) {
            int mt = wr + 4 * j;
            int m = mt * 16 + mrow;
            if (m > 195) m = 195;
            int py = m / 14, px = m - py * 14;
            P0[j] = (py + 1) * 16 + (px + 1);
        }
    }
    int acgl = (lane >> 4) & 1;                        // A cg parity per lane
    int bnl  = ((lane >> 4) & 1) * 8 + (lane & 7);     // B row-within-16 per lane
    int bg0  = (lane >> 3) & 1;                        // B cg parity per lane

    float acc[4][8][4];
    #pragma unroll
    for (int j = 0; j < 4; ++j)
        #pragma unroll
        for (int t = 0; t < 8; ++t)
            #pragma unroll
            for (int e = 0; e < 4; ++e) acc[j][t][e] = 0.f;

    const float* inb = in + (size_t)nb * HWD * HWD * CIN;
    int h0 = by * OBS - 1;
    int w0 = bx * OBS - 1;

    // ---- prologue: stage B(0) (cc=0, seg=0, tap=0) ----
    {
        const __nv_bfloat16* wb = g_W2;   // seg0, tap0, c0
        #pragma unroll
        for (int j = 0; j < 4; ++j) {
            int u = tid + j * 256;
            int n = u >> 3, g = u & 7;
            uint4 v = *(const uint4*)(wb + (size_t)(fbase + n) * KP + g * 8);
            *(uint4*)(smem + BOFF + n * 128 + (((g ^ (n & 7))) << 4)) = v;
        }
    }

    for (int i = 0; i < NITER; ++i) {
        int cc = i / 27;
        int r = i - cc * 27;
        int seg = r / 9;
        int tap = r - seg * 9;
        int buf = i & 1;

        if (r == 0) {
            // new channel chunk: load 16x16 window (hi+lo) for 64 channels
            __syncthreads();     // all compute on old window done
            int c0 = cc * 64;
            #pragma unroll
            for (int j = 0; j < 8; ++j) {
                int u = tid + j * 256;       // (pixel, 16B group)
                int p = u >> 3, g = u & 7;
                int y = p >> 4, x = p & 15;
                int gy = h0 + y, gx = w0 + x;
                float v[8];
                #pragma unroll
                for (int e = 0; e < 8; ++e) v[e] = 0.f;
                if ((unsigned)gy < HWD && (unsigned)gx < HWD) {
                    const float* sp = inb + (((size_t)gy * HWD + gx) * CIN) + c0 + g * 8;
                    float4 va = ((const float4*)sp)[0];
                    float4 vb = ((const float4*)sp)[1];
                    v[0] = va.x; v[1] = va.y; v[2] = va.z; v[3] = va.w;
                    v[4] = vb.x; v[5] = vb.y; v[6] = vb.z; v[7] = vb.w;
                }
                union { __nv_bfloat16 bf[8]; uint4 u4; } H, L;
                #pragma unroll
                for (int e = 0; e < 8; ++e) {
                    __nv_bfloat16 hh = __float2bfloat16(v[e]);
                    H.bf[e] = hh;
                    L.bf[e] = __float2bfloat16(v[e] - __bfloat162float(hh));
                }
                uint32_t so = p * 128 + (((g ^ (p & 7))) << 4);
                *(uint4*)(smem + WIN_HI + so) = H.u4;
                *(uint4*)(smem + WIN_LO + so) = L.u4;
            }
        }

        // prefetch next B stage into registers
        uint4 br[4];
        if (i + 1 < NITER) {
            int i2 = i + 1;
            int cc2 = i2 / 27;
            int r2 = i2 - cc2 * 27;
            int seg2 = r2 / 9;
            int tap2 = r2 - seg2 * 9;
            const __nv_bfloat16* wb = g_W2 + seg2 * KTOT + tap2 * 256 + cc2 * 64;
            #pragma unroll
            for (int j = 0; j < 4; ++j) {
                int u = tid + j * 256;
                int n = u >> 3, g = u & 7;
                br[j] = *(const uint4*)(wb + (size_t)(fbase + n) * KP + g * 8);
            }
        }

        __syncthreads();   // window + B(i) stores visible; buf (i+1)&1 free

        // ---- compute this (seg, tap) stage: 4 k16 steps ----
        int dy = tap / 3 - 1, dx = tap - (tap / 3) * 3 - 1;
        int doff = dy * 16 + dx;
        uint32_t winb = sbase + ((seg == 1) ? WIN_LO : WIN_HI);
        uint32_t bbuf = sbase + BOFF + buf * 16384;

        #pragma unroll
        for (int kk = 0; kk < 4; ++kk) {
            // B fragments: n64 for this warp = 4 x LDSM4
            uint32_t bfr[4][4];
            int bcg = 2 * kk + bg0;
            #pragma unroll
            for (int u = 0; u < 4; ++u) {
                int bn = wc * 64 + u * 16 + bnl;
                uint32_t ba = bbuf + (uint32_t)bn * 128 + (((bcg ^ (bn & 7))) << 4);
                LDSM4(bfr[u][0], bfr[u][1], bfr[u][2], bfr[u][3], ba);
            }
            int acg = 2 * kk + acgl;
            #pragma unroll
            for (int j = 0; j < 4; ++j) {
                if (wr + 4 * j < 13) {
                    int P = P0[j] + doff;
                    uint32_t aa = winb + (uint32_t)P * 128 + (((acg ^ (P & 7))) << 4);
                    uint32_t a0, a1, a2, a3;
                    LDSM4(a0, a1, a2, a3, aa);
                    #pragma unroll
                    for (int u = 0; u < 4; ++u) {
                        MMA16816(acc[j][u * 2 + 0], a0, a1, a2, a3, bfr[u][0], bfr[u][1]);
                        MMA16816(acc[j][u * 2 + 1], a0, a1, a2, a3, bfr[u][2], bfr[u][3]);
                    }
                }
            }
        }

        // store prefetched B(i+1)
        if (i + 1 < NITER) {
            uint32_t dst = BOFF + ((i + 1) & 1) * 16384;
            #pragma unroll
            for (int j = 0; j < 4; ++j) {
                int u = tid + j * 256;
                int n = u >> 3, g = u & 7;
                *(uint4*)(smem + dst + n * 128 + (((g ^ (n & 7))) << 4)) = br[j];
            }
        }
    }

    // ---- epilogue: bias + relu + store ----
    const float* sb = (const float*)(smem + BIASOF);
    #pragma unroll
    for (int j = 0; j < 4; ++j) {
        int mt = wr + 4 * j;
        if (mt < 13) {
            #pragma unroll
            for (int u = 0; u < 4; ++u) {
                #pragma unroll
                for (int hf = 0; hf < 2; ++hf) {
                    int nn = wc * 64 + u * 16 + hf * 8 + (lane & 3) * 2;
                    float bz0 = sb[nn], bz1 = sb[nn + 1];
                    #pragma unroll
                    for (int h2 = 0; h2 < 2; ++h2) {
                        int m = mt * 16 + (lane >> 2) + h2 * 8;
                        if (m < 196) {
                            int py = m / 14, px = m - py * 14;
                            float* o = out + (((size_t)nb * HWD + by * OBS + py) * HWD
                                              + bx * OBS + px) * FOUT + fbase + nn;
                            float2 v;
                            v.x = fmaxf(acc[j][u * 2 + hf][h2 * 2 + 0] + bz0, 0.f);
                            v.y = fmaxf(acc[j][u * 2 + hf][h2 * 2 + 1] + bz1, 0.f);
                            *(float2*)o = v;
                        }
                    }
                }
            }
        }
    }
}

extern "C" void kernel_launch(void* const* d_in, const int* in_sizes, int n_in,
                              void* d_out, int out_size) {
    (void)in_sizes; (void)n_in; (void)out_size;
    const float* in   = (const float*)d_in[0];   // (4,224,224,256)
    const float* mask = (const float*)d_in[1];   // (4,224,224,1)
    const float* wgt  = (const float*)d_in[2];   // (3,3,256,256)
    const float* bias = (const float*)d_in[3];   // (256,)
    float* out = (float*)d_out;

    cudaFuncSetAttribute(conv_mma_kernel,
                         cudaFuncAttributeMaxDynamicSharedMemorySize, SMEM_TOTAL);
    active_kernel<<<1024, 256>>>(mask);
    wprep_kernel<<<2304, 256>>>(wgt);
    dim3 grid(1024, 2);
    conv_mma_kernel<<<grid, 256, SMEM_TOTAL>>>(in, bias, out);
}

// round 5
// speedup vs baseline: 9.1355x; 2.6477x over previous
#include <cuda_runtime.h>
#include <cuda_fp16.h>
#include <cstdint>
#include <cstddef>

#define HWD  224
#define CIN  256
#define FOUT 256
#define OBS  14
#define KTOT 2304            // 9 taps * 256 c
#define NCHUNK 4             // 256 c / 64
#define NITER (NCHUNK * 9)   // 36 (cc, tap) stages, 4 k16-steps each

// smem layout (bytes)
#define WIN    0             // 16x16 px * 64 c * fp16 = 32768
#define BOFF   32768         // 2 x 16384 B stage buffers
#define BIASOF 65536
#define SMEM_TOTAL 66048

__device__ int g_active[1024];
__device__ __align__(16) __half g_W2[256 * KTOT];   // [f][tap*256 + c]

__device__ __forceinline__ uint32_t smem_to_u32(const void* p) {
    uint32_t a;
    asm("{ .reg .u64 t; cvta.to.shared.u64 t, %1; cvt.u32.u64 %0, t; }" : "=r"(a) : "l"(p));
    return a;
}

#define LDSM4(r0, r1, r2, r3, addr) \
    asm volatile("ldmatrix.sync.aligned.m8n8.x4.shared.b16 {%0,%1,%2,%3}, [%4];" \
        : "=r"(r0), "=r"(r1), "=r"(r2), "=r"(r3) : "r"(addr))

#define MMA16816(d, a0, a1, a2, a3, b0, b1) \
    asm volatile("mma.sync.aligned.m16n8k16.row.col.f32.f16.f16.f32 " \
        "{%0,%1,%2,%3}, {%4,%5,%6,%7}, {%8,%9}, {%0,%1,%2,%3};" \
        : "+f"((d)[0]), "+f"((d)[1]), "+f"((d)[2]), "+f"((d)[3]) \
        : "r"(a0), "r"(a1), "r"(a2), "r"(a3), "r"(b0), "r"(b1))

// ---------------------------------------------------------------------------
// Kernel 1: block activity
// ---------------------------------------------------------------------------
__global__ void active_kernel(const float* __restrict__ mask) {
    int b = blockIdx.x;
    int nb = b >> 8, by = (b >> 4) & 15, bx = b & 15;
    int t = threadIdx.x;
    int ty = t >> 4, tx = t & 15;
    int h = by * OBS - 1 + ty;
    int w = bx * OBS - 1 + tx;
    float v = 0.f;
    if (h >= 0 && h < HWD && w >= 0 && w < HWD)
        v = mask[(nb * HWD + h) * HWD + w];
    double d = (double)v;
    #pragma unroll
    for (int o = 16; o > 0; o >>= 1)
        d += __shfl_down_sync(0xffffffffu, d, o);
    __shared__ double sred[8];
    if ((t & 31) == 0) sred[t >> 5] = d;
    __syncthreads();
    if (t == 0) {
        double s = 0.0;
        #pragma unroll
        for (int i = 0; i < 8; ++i) s += sred[i];
        g_active[b] = (s * (1.0 / 256.0) > 0.5) ? 1 : 0;
    }
}

// ---------------------------------------------------------------------------
// Kernel 2: weight transpose to fp16: g_W2[f][k], k = tap*256 + c
// ---------------------------------------------------------------------------
__global__ void wprep_kernel(const float* __restrict__ wgt) {
    int idx = blockIdx.x * 256 + threadIdx.x;   // 0 .. 2304*256-1
    int f = idx & 255;
    int k = idx >> 8;
    g_W2[(size_t)f * KTOT + k] = __float2half_rn(wgt[(size_t)k * 256 + f]);
}

// ---------------------------------------------------------------------------
// Kernel 3: per-(active block, 128-filter half) implicit conv GEMM via
// mma.sync fp16. 8 warps tiled 4(m) x 2(n): each warp n64 x up-to-4 m16 tiles.
// ---------------------------------------------------------------------------
__global__ void __launch_bounds__(256, 1)
conv_mma_kernel(const float* __restrict__ in, const float* __restrict__ bias,
                float* __restrict__ out) {
    int b = blockIdx.x;
    int fhalf = blockIdx.y;
    int nb = b >> 8, by = (b >> 4) & 15, bx = b & 15;
    int tid = threadIdx.x;
    int fbase = fhalf * 128;

    if (!g_active[b]) {
        if (tid < 196) {
            int Y = by * OBS + tid / OBS, X = bx * OBS + tid % OBS;
            float4* o = (float4*)(out + (((size_t)nb * HWD + Y) * HWD + X) * FOUT + fbase);
            float4 z = make_float4(0.f, 0.f, 0.f, 0.f);
            #pragma unroll
            for (int i = 0; i < 32; ++i) o[i] = z;
        }
        return;
    }

    extern __shared__ char smem[];
    uint32_t sbase = smem_to_u32(smem);
    int warp = tid >> 5, lane = tid & 31;
    int wr = warp & 3;          // m row-group
    int wc = warp >> 2;         // n column-group (n64)

    // bias slice to smem
    if (tid < 32) ((float4*)(smem + BIASOF))[tid] = ((const float4*)(bias + fbase))[tid];

    // per-lane A-row table: ldmatrix row for each of this warp's m-tiles
    int P0[4];
    {
        int mrow = (lane & 7) + ((lane >> 3) & 1) * 8;
        #pragma unroll
        for (int j = 0; j < 4; ++j) {
            int mt = wr + 4 * j;
            int m = mt * 16 + mrow;
            if (m > 195) m = 195;
            int py = m / 14, px = m - py * 14;
            P0[j] = (py + 1) * 16 + (px + 1);
        }
    }
    int acgl = (lane >> 4) & 1;                        // A cg parity per lane
    int bnl  = ((lane >> 4) & 1) * 8 + (lane & 7);     // B row-within-16 per lane
    int bg0  = (lane >> 3) & 1;                        // B cg parity per lane

    float acc[4][8][4];
    #pragma unroll
    for (int j = 0; j < 4; ++j)
        #pragma unroll
        for (int t = 0; t < 8; ++t)
            #pragma unroll
            for (int e = 0; e < 4; ++e) acc[j][t][e] = 0.f;

    const float* inb = in + (size_t)nb * HWD * HWD * CIN;
    int h0 = by * OBS - 1;
    int w0 = bx * OBS - 1;

    // ---- prologue: stage B(0) (cc=0, tap=0) ----
    {
        const __half* wb = g_W2;
        #pragma unroll
        for (int j = 0; j < 4; ++j) {
            int u = tid + j * 256;
            int n = u >> 3, g = u & 7;
            uint4 v = *(const uint4*)(wb + (size_t)(fbase + n) * KTOT + g * 8);
            *(uint4*)(smem + BOFF + n * 128 + (((g ^ (n & 7))) << 4)) = v;
        }
    }

    for (int i = 0; i < NITER; ++i) {
        int cc = i / 9;
        int tap = i - cc * 9;
        int buf = i & 1;

        if (tap == 0) {
            // new channel chunk: load 16x16 window (fp16) for 64 channels
            __syncthreads();     // all compute on old window done
            int c0 = cc * 64;
            #pragma unroll
            for (int j = 0; j < 8; ++j) {
                int u = tid + j * 256;       // (pixel, 16B group)
                int p = u >> 3, g = u & 7;
                int y = p >> 4, x = p & 15;
                int gy = h0 + y, gx = w0 + x;
                float v[8];
                #pragma unroll
                for (int e = 0; e < 8; ++e) v[e] = 0.f;
                if ((unsigned)gy < HWD && (unsigned)gx < HWD) {
                    const float* sp = inb + (((size_t)gy * HWD + gx) * CIN) + c0 + g * 8;
                    float4 va = ((const float4*)sp)[0];
                    float4 vb = ((const float4*)sp)[1];
                    v[0] = va.x; v[1] = va.y; v[2] = va.z; v[3] = va.w;
                    v[4] = vb.x; v[5] = vb.y; v[6] = vb.z; v[7] = vb.w;
                }
                union { __half hf[8]; uint4 u4; } H;
                #pragma unroll
                for (int e = 0; e < 8; ++e) H.hf[e] = __float2half_rn(v[e]);
                uint32_t so = p * 128 + (((g ^ (p & 7))) << 4);
                *(uint4*)(smem + WIN + so) = H.u4;
            }
        }

        // prefetch next B stage into registers
        uint4 br[4];
        if (i + 1 < NITER) {
            int i2 = i + 1;
            int cc2 = i2 / 9;
            int tap2 = i2 - cc2 * 9;
            const __half* wb = g_W2 + tap2 * 256 + cc2 * 64;
            #pragma unroll
            for (int j = 0; j < 4; ++j) {
                int u = tid + j * 256;
                int n = u >> 3, g = u & 7;
                br[j] = *(const uint4*)(wb + (size_t)(fbase + n) * KTOT + g * 8);
            }
        }

        __syncthreads();   // window + B(i) stores visible; buf (i+1)&1 free

        // ---- compute this tap stage: 4 k16 steps ----
        int dy = tap / 3 - 1, dx = tap - (tap / 3) * 3 - 1;
        int doff = dy * 16 + dx;
        uint32_t winb = sbase + WIN;
        uint32_t bbuf = sbase + BOFF + buf * 16384;

        #pragma unroll
        for (int kk = 0; kk < 4; ++kk) {
            // B fragments: n64 for this warp = 4 x LDSM4
            uint32_t bfr[4][4];
            int bcg = 2 * kk + bg0;
            #pragma unroll
            for (int u = 0; u < 4; ++u) {
                int bn = wc * 64 + u * 16 + bnl;
                uint32_t ba = bbuf + (uint32_t)bn * 128 + (((bcg ^ (bn & 7))) << 4);
                LDSM4(bfr[u][0], bfr[u][1], bfr[u][2], bfr[u][3], ba);
            }
            int acg = 2 * kk + acgl;
            #pragma unroll
            for (int j = 0; j < 4; ++j) {
                if (wr + 4 * j < 13) {
                    int P = P0[j] + doff;
                    uint32_t aa = winb + (uint32_t)P * 128 + (((acg ^ (P & 7))) << 4);
                    uint32_t a0, a1, a2, a3;
                    LDSM4(a0, a1, a2, a3, aa);
                    #pragma unroll
                    for (int u = 0; u < 4; ++u) {
                        MMA16816(acc[j][u * 2 + 0], a0, a1, a2, a3, bfr[u][0], bfr[u][1]);
                        MMA16816(acc[j][u * 2 + 1], a0, a1, a2, a3, bfr[u][2], bfr[u][3]);
                    }
                }
            }
        }

        // store prefetched B(i+1)
        if (i + 1 < NITER) {
            uint32_t dst = BOFF + ((i + 1) & 1) * 16384;
            #pragma unroll
            for (int j = 0; j < 4; ++j) {
                int u = tid + j * 256;
                int n = u >> 3, g = u & 7;
                *(uint4*)(smem + dst + n * 128 + (((g ^ (n & 7))) << 4)) = br[j];
            }
        }
    }

    // ---- epilogue: bias + relu + store ----
    const float* sb = (const float*)(smem + BIASOF);
    #pragma unroll
    for (int j = 0; j < 4; ++j) {
        int mt = wr + 4 * j;
        if (mt < 13) {
            #pragma unroll
            for (int u = 0; u < 4; ++u) {
                #pragma unroll
                for (int hf = 0; hf < 2; ++hf) {
                    int nn = wc * 64 + u * 16 + hf * 8 + (lane & 3) * 2;
                    float bz0 = sb[nn], bz1 = sb[nn + 1];
                    #pragma unroll
                    for (int h2 = 0; h2 < 2; ++h2) {
                        int m = mt * 16 + (lane >> 2) + h2 * 8;
                        if (m < 196) {
                            int py = m / 14, px = m - py * 14;
                            float* o = out + (((size_t)nb * HWD + by * OBS + py) * HWD
                                              + bx * OBS + px) * FOUT + fbase + nn;
                            float2 v;
                            v.x = fmaxf(acc[j][u * 2 + hf][h2 * 2 + 0] + bz0, 0.f);
                            v.y = fmaxf(acc[j][u * 2 + hf][h2 * 2 + 1] + bz1, 0.f);
                            *(float2*)o = v;
                        }
                    }
                }
            }
        }
    }
}

extern "C" void kernel_launch(void* const* d_in, const int* in_sizes, int n_in,
                              void* d_out, int out_size) {
    (void)in_sizes; (void)n_in; (void)out_size;
    const float* in   = (const float*)d_in[0];   // (4,224,224,256)
    const float* mask = (const float*)d_in[1];   // (4,224,224,1)
    const float* wgt  = (const float*)d_in[2];   // (3,3,256,256)
    const float* bias = (const float*)d_in[3];   // (256,)
    float* out = (float*)d_out;

    cudaFuncSetAttribute(conv_mma_kernel,
                         cudaFuncAttributeMaxDynamicSharedMemorySize, SMEM_TOTAL);
    active_kernel<<<1024, 256>>>(mask);
    wprep_kernel<<<2304, 256>>>(wgt);
    dim3 grid(1024, 2);
    conv_mma_kernel<<<grid, 256, SMEM_TOTAL>>>(in, bias, out);
}

// round 7
// speedup vs baseline: 9.6987x; 1.0616x over previous
#include <cuda_runtime.h>
#include <cuda_fp16.h>
#include <cstdint>
#include <cstddef>

#define HWD  224
#define CIN  256
#define FOUT 256
#define OBS  14
#define KTOT 2304            // 9 taps * 256 c
#define NSTG 12              // 4 chunks * 3 stages; stage = 3 taps * 4 k16-steps

// smem layout (bytes)
#define WIN0   0             // two 16x16x64c fp16 windows (32 KB each)
#define BOFF   65536         // 3 cyclic B buffers, 48 KB each (3 taps x 16 KB)
#define BIASOF 212992
#define SMEM_TOTAL 213504

__device__ int g_active[1024];
__device__ __align__(16) __half g_W2[256 * KTOT];   // [f][tap*256 + c]

__device__ __forceinline__ uint32_t smem_to_u32(const void* p) {
    uint32_t a;
    asm("{ .reg .u64 t; cvta.to.shared.u64 t, %1; cvt.u32.u64 %0, t; }" : "=r"(a) : "l"(p));
    return a;
}

#define LDSM4(r0, r1, r2, r3, addr) \
    asm volatile("ldmatrix.sync.aligned.m8n8.x4.shared.b16 {%0,%1,%2,%3}, [%4];" \
        : "=r"(r0), "=r"(r1), "=r"(r2), "=r"(r3) : "r"(addr))

#define MMA16816(d, a0, a1, a2, a3, b0, b1) \
    asm volatile("mma.sync.aligned.m16n8k16.row.col.f32.f16.f16.f32 " \
        "{%0,%1,%2,%3}, {%4,%5,%6,%7}, {%8,%9}, {%0,%1,%2,%3};" \
        : "+f"((d)[0]), "+f"((d)[1]), "+f"((d)[2]), "+f"((d)[3]) \
        : "r"(a0), "r"(a1), "r"(a2), "r"(a3), "r"(b0), "r"(b1))

#define CP_ASYNC16(dst, src) \
    asm volatile("cp.async.cg.shared.global [%0], [%1], 16;" \
        :: "r"((uint32_t)(dst)), "l"(src) : "memory")
#define CP_COMMIT() asm volatile("cp.async.commit_group;" ::: "memory")
#define CP_WAIT1()  asm volatile("cp.async.wait_group 1;" ::: "memory")

// ---------------------------------------------------------------------------
// Kernel 1: block activity
// ---------------------------------------------------------------------------
__global__ void active_kernel(const float* __restrict__ mask) {
    int b = blockIdx.x;
    int nb = b >> 8, by = (b >> 4) & 15, bx = b & 15;
    int t = threadIdx.x;
    int ty = t >> 4, tx = t & 15;
    int h = by * OBS - 1 + ty;
    int w = bx * OBS - 1 + tx;
    float v = 0.f;
    if (h >= 0 && h < HWD && w >= 0 && w < HWD)
        v = mask[(nb * HWD + h) * HWD + w];
    double d = (double)v;
    #pragma unroll
    for (int o = 16; o > 0; o >>= 1)
        d += __shfl_down_sync(0xffffffffu, d, o);
    __shared__ double sred[8];
    if ((t & 31) == 0) sred[t >> 5] = d;
    __syncthreads();
    if (t == 0) {
        double s = 0.0;
        #pragma unroll
        for (int i = 0; i < 8; ++i) s += sred[i];
        g_active[b] = (s * (1.0 / 256.0) > 0.5) ? 1 : 0;
    }
}

// ---------------------------------------------------------------------------
// Kernel 2: weight transpose to fp16: g_W2[f][k], k = tap*256 + c
// ---------------------------------------------------------------------------
__global__ void wprep_kernel(const float* __restrict__ wgt) {
    int idx = blockIdx.x * 256 + threadIdx.x;
    int f = idx & 255;
    int k = idx >> 8;
    g_W2[(size_t)f * KTOT + k] = __float2half_rn(wgt[(size_t)k * 256 + f]);
}

// ---------------------------------------------------------------------------
// Kernel 3: per-(active block, 128-filter half) implicit conv GEMM.
// 8 warps: wc=warp&3 (n32, SMSP-balanced), wr=warp>>2 (m-tiles 0-6 / 7-12).
// B: cp.async 3-deep cyclic, 3 taps/stage. Window: fp16, double-buffered.
// ---------------------------------------------------------------------------
__global__ void __launch_bounds__(256, 1)
conv_mma_kernel(const float* __restrict__ in, const float* __restrict__ bias,
                float* __restrict__ out) {
    int b = blockIdx.x;
    int fhalf = blockIdx.y;
    int nb = b >> 8, by = (b >> 4) & 15, bx = b & 15;
    int tid = threadIdx.x;
    int fbase = fhalf * 128;

    if (!g_active[b]) {
        if (tid < 196) {
            int Y = by * OBS + tid / OBS, X = bx * OBS + tid % OBS;
            float4* o = (float4*)(out + (((size_t)nb * HWD + Y) * HWD + X) * FOUT + fbase);
            float4 z = make_float4(0.f, 0.f, 0.f, 0.f);
            #pragma unroll
            for (int i = 0; i < 32; ++i) o[i] = z;
        }
        return;
    }

    extern __shared__ char smem[];
    uint32_t sbase = smem_to_u32(smem);
    int warp = tid >> 5, lane = tid & 31;
    int wc = warp & 3;          // n column-group (n32) -> SMSP-balanced
    int wr = warp >> 2;         // m row-group: tiles wr*7 .. wr*7+6 (wr=1: 6 tiles)

    if (tid < 32) ((float4*)(smem + BIASOF))[tid] = ((const float4*)(bias + fbase))[tid];

    // per-lane A-row table
    int P0[7];
    {
        int mrow = (lane & 7) + ((lane >> 3) & 1) * 8;
        #pragma unroll
        for (int j = 0; j < 7; ++j) {
            int mt = wr * 7 + j;
            int m = mt * 16 + mrow;
            if (m > 195) m = 195;
            int py = m / 14, px = m - py * 14;
            P0[j] = (py + 1) * 16 + (px + 1);
        }
    }
    int acgl = (lane >> 4) & 1;
    int bnl  = ((lane >> 4) & 1) * 8 + (lane & 7);
    int bg0  = (lane >> 3) & 1;

    float acc[7][4][4];
    #pragma unroll
    for (int j = 0; j < 7; ++j)
        #pragma unroll
        for (int t = 0; t < 4; ++t)
            #pragma unroll
            for (int e = 0; e < 4; ++e) acc[j][t][e] = 0.f;

    const float* inb = in + (size_t)nb * HWD * HWD * CIN;
    int h0 = by * OBS - 1;
    int w0 = bx * OBS - 1;

    // window loader (fp32 LDG -> fp16 cvt -> STS into winbuf wb for chunk cc)
    auto load_window = [&](int cc, int wb) {
        int c0 = cc * 64;
        char* wdst = smem + WIN0 + wb * 32768;
        #pragma unroll
        for (int j = 0; j < 8; ++j) {
            int u = tid + j * 256;
            int p = u >> 3, g = u & 7;
            int y = p >> 4, x = p & 15;
            int gy = h0 + y, gx = w0 + x;
            float v[8];
            #pragma unroll
            for (int e = 0; e < 8; ++e) v[e] = 0.f;
            if ((unsigned)gy < HWD && (unsigned)gx < HWD) {
                const float* sp = inb + (((size_t)gy * HWD + gx) * CIN) + c0 + g * 8;
                float4 va = ((const float4*)sp)[0];
                float4 vb = ((const float4*)sp)[1];
                v[0] = va.x; v[1] = va.y; v[2] = va.z; v[3] = va.w;
                v[4] = vb.x; v[5] = vb.y; v[6] = vb.z; v[7] = vb.w;
            }
            union { __half hf[8]; uint4 u4; } H;
            #pragma unroll
            for (int e = 0; e < 8; ++e) H.hf[e] = __float2half_rn(v[e]);
            *(uint4*)(wdst + p * 128 + (((g ^ (p & 7))) << 4)) = H.u4;
        }
    };

    // B stage issuer: stage t -> buffer t%3 (12 cp.async of 16B per thread)
    auto issue_B = [&](int t) {
        int cct = t / 3, tbt = (t % 3) * 3;
        uint32_t bufb = sbase + BOFF + (uint32_t)(t % 3) * 49152;
        const __half* wsrc = g_W2 + tbt * 256 + cct * 64;
        #pragma unroll
        for (int j = 0; j < 12; ++j) {
            int u = tid + j * 256;
            int tl = u >> 10;
            int rem = u & 1023;
            int n = rem >> 3, g = rem & 7;
            const __half* src = wsrc + (size_t)(fbase + n) * KTOT + tl * 256 + g * 8;
            uint32_t dst = bufb + tl * 16384 + n * 128 + (((g ^ (n & 7))) << 4);
            CP_ASYNC16(dst, src);
        }
    };

    // prologue: B(0) in flight, window chunk 0 into winbuf 0
    issue_B(0);
    CP_COMMIT();
    load_window(0, 0);

    for (int s = 0; s < NSTG; ++s) {
        int cc = s / 3;
        int tb = (s % 3) * 3;

        // keep pipeline: issue B(s+1) (empty commit on last stage is fine)
        if (s + 1 < NSTG) issue_B(s + 1);
        CP_COMMIT();
        CP_WAIT1();            // B(s) complete locally
        __syncthreads();       // publish B(s) + any window/bias STS; compute(s-1) done

        // prefetch next chunk's window into the other winbuf (published next sync)
        if ((s % 3) == 2 && cc + 1 < 4) load_window(cc + 1, (cc + 1) & 1);

        uint32_t winb = sbase + WIN0 + (uint32_t)(cc & 1) * 32768;
        uint32_t bbuf = sbase + BOFF + (uint32_t)(s % 3) * 49152;

        #pragma unroll
        for (int tl = 0; tl < 3; ++tl) {
            int tap = tb + tl;
            int dy = tap / 3 - 1, dx = tap - (tap / 3) * 3 - 1;
            int doff = dy * 16 + dx;
            uint32_t btap = bbuf + tl * 16384;
            #pragma unroll
            for (int kk = 0; kk < 4; ++kk) {
                uint32_t bfr[2][4];
                int bcg = 2 * kk + bg0;
                #pragma unroll
                for (int u = 0; u < 2; ++u) {
                    int bn = wc * 32 + u * 16 + bnl;
                    uint32_t ba = btap + (uint32_t)bn * 128 + (((bcg ^ (bn & 7))) << 4);
                    LDSM4(bfr[u][0], bfr[u][1], bfr[u][2], bfr[u][3], ba);
                }
                int acg = 2 * kk + acgl;
                #pragma unroll
                for (int j = 0; j < 7; ++j) {
                    if (wr * 7 + j < 13) {
                        int P = P0[j] + doff;
                        uint32_t aa = winb + (uint32_t)P * 128 + (((acg ^ (P & 7))) << 4);
                        uint32_t a0, a1, a2, a3;
                        LDSM4(a0, a1, a2, a3, aa);
                        #pragma unroll
                        for (int u = 0; u < 2; ++u) {
                            MMA16816(acc[j][u * 2 + 0], a0, a1, a2, a3, bfr[u][0], bfr[u][1]);
                            MMA16816(acc[j][u * 2 + 1], a0, a1, a2, a3, bfr[u][2], bfr[u][3]);
                        }
                    }
                }
            }
        }
    }

    // ---- epilogue: bias + relu + store ----
    const float* sb = (const float*)(smem + BIASOF);
    #pragma unroll
    for (int j = 0; j < 7; ++j) {
        int mt = wr * 7 + j;
        if (mt < 13) {
            #pragma unroll
            for (int u = 0; u < 2; ++u) {
                #pragma unroll
                for (int hf = 0; hf < 2; ++hf) {
                    int nn = wc * 32 + u * 16 + hf * 8 + (lane & 3) * 2;
                    float bz0 = sb[nn], bz1 = sb[nn + 1];
                    #pragma unroll
                    for (int h2 = 0; h2 < 2; ++h2) {
                        int m = mt * 16 + (lane >> 2) + h2 * 8;
                        if (m < 196) {
                            int py = m / 14, px = m - py * 14;
                            float* o = out + (((size_t)nb * HWD + by * OBS + py) * HWD
                                              + bx * OBS + px) * FOUT + fbase + nn;
                            float2 v;
                            v.x = fmaxf(acc[j][u * 2 + hf][h2 * 2 + 0] + bz0, 0.f);
                            v.y = fmaxf(acc[j][u * 2 + hf][h2 * 2 + 1] + bz1, 0.f);
                            *(float2*)o = v;
                        }
                    }
                }
            }
        }
    }
}

extern "C" void kernel_launch(void* const* d_in, const int* in_sizes, int n_in,
                              void* d_out, int out_size) {
    (void)in_sizes; (void)n_in; (void)out_size;
    const float* in   = (const float*)d_in[0];   // (4,224,224,256)
    const float* mask = (const float*)d_in[1];   // (4,224,224,1)
    const float* wgt  = (const float*)d_in[2];   // (3,3,256,256)
    const float* bias = (const float*)d_in[3];   // (256,)
    float* out = (float*)d_out;

    cudaFuncSetAttribute(conv_mma_kernel,
                         cudaFuncAttributeMaxDynamicSharedMemorySize, SMEM_TOTAL);
    active_kernel<<<1024, 256>>>(mask);
    wprep_kernel<<<2304, 256>>>(wgt);
    dim3 grid(1024, 2);
    conv_mma_kernel<<<grid, 256, SMEM_TOTAL>>>(in, bias, out);
}

// round 8
// speedup vs baseline: 10.1221x; 1.0437x over previous
#include <cuda_runtime.h>
#include <cuda_fp16.h>
#include <cstdint>
#include <cstddef>

#define HWD  224
#define CIN  256
#define FOUT 256
#define OBS  14
#define KTOT 2304            // 9 taps * 256 c
#define NSTG 12              // 4 chunks * 3 stages; stage = 3 taps * 4 k16-steps

// smem layout (bytes)
#define WIN0   0             // two 16x16x64c fp16 windows (32 KB each)
#define BOFF   65536         // 3 cyclic B buffers, 48 KB each (3 taps x 16 KB)
#define BIASOF 212992        // 512 B
#define REDOF  213504        // mask-reduce scratch (64B sums + flag)
#define SMEM_TOTAL 213632

__device__ __align__(16) __half g_W2[256 * KTOT];   // [f][tap*256 + c]

__device__ __forceinline__ uint32_t smem_to_u32(const void* p) {
    uint32_t a;
    asm("{ .reg .u64 t; cvta.to.shared.u64 t, %1; cvt.u32.u64 %0, t; }" : "=r"(a) : "l"(p));
    return a;
}

#define LDSM4(r0, r1, r2, r3, addr) \
    asm volatile("ldmatrix.sync.aligned.m8n8.x4.shared.b16 {%0,%1,%2,%3}, [%4];" \
        : "=r"(r0), "=r"(r1), "=r"(r2), "=r"(r3) : "r"(addr))

#define MMA16816(d, a0, a1, a2, a3, b0, b1) \
    asm volatile("mma.sync.aligned.m16n8k16.row.col.f32.f16.f16.f32 " \
        "{%0,%1,%2,%3}, {%4,%5,%6,%7}, {%8,%9}, {%0,%1,%2,%3};" \
        : "+f"((d)[0]), "+f"((d)[1]), "+f"((d)[2]), "+f"((d)[3]) \
        : "r"(a0), "r"(a1), "r"(a2), "r"(a3), "r"(b0), "r"(b1))

#define CP_ASYNC16(dst, src) \
    asm volatile("cp.async.cg.shared.global [%0], [%1], 16;" \
        :: "r"((uint32_t)(dst)), "l"(src) : "memory")
#define CP_COMMIT() asm volatile("cp.async.commit_group;" ::: "memory")
#define CP_WAIT1()  asm volatile("cp.async.wait_group 1;" ::: "memory")

// ---------------------------------------------------------------------------
// Weight transpose to fp16: g_W2[f][k], k = tap*256 + c
// ---------------------------------------------------------------------------
__global__ void wprep_kernel(const float* __restrict__ wgt) {
    int idx = blockIdx.x * 256 + threadIdx.x;
    int f = idx & 255;
    int k = idx >> 8;
    g_W2[(size_t)f * KTOT + k] = __float2half_rn(wgt[(size_t)k * 256 + f]);
}

// ---------------------------------------------------------------------------
// Pipelined per-tap compute: 4 k16-steps; NT m-tiles (7 or 6, compile-time).
// B ldmatrix first, then A(j+1) prefetched under A(j)'s 4 MMAs.
// ---------------------------------------------------------------------------
template<int NT>
__device__ __forceinline__ void compute_tap(
    float acc[7][4][4],
    uint32_t winb, uint32_t btap,
    const uint32_t* __restrict__ arow, const uint32_t* __restrict__ ap7,
    const uint32_t* __restrict__ brow, const uint32_t* __restrict__ bp7,
    int acgl, int bg0)
{
    #pragma unroll
    for (int kk = 0; kk < 4; ++kk) {
        uint32_t bfr[2][4];
        int bcg = 2 * kk + bg0;
        #pragma unroll
        for (int u = 0; u < 2; ++u) {
            uint32_t ba = btap + brow[u] + (uint32_t)(((bcg ^ bp7[u])) << 4);
            LDSM4(bfr[u][0], bfr[u][1], bfr[u][2], bfr[u][3], ba);
        }
        int acg = 2 * kk + acgl;
        uint32_t a0, a1, a2, a3;
        {
            uint32_t aa = winb + arow[0] + (uint32_t)(((acg ^ ap7[0])) << 4);
            LDSM4(a0, a1, a2, a3, aa);
        }
        #pragma unroll
        for (int j = 0; j < NT; ++j) {
            uint32_t n0, n1, n2, n3;
            if (j + 1 < NT) {
                uint32_t aa = winb + arow[j + 1] + (uint32_t)(((acg ^ ap7[j + 1])) << 4);
                LDSM4(n0, n1, n2, n3, aa);
            }
            MMA16816(acc[j][0], a0, a1, a2, a3, bfr[0][0], bfr[0][1]);
            MMA16816(acc[j][1], a0, a1, a2, a3, bfr[0][2], bfr[0][3]);
            MMA16816(acc[j][2], a0, a1, a2, a3, bfr[1][0], bfr[1][1]);
            MMA16816(acc[j][3], a0, a1, a2, a3, bfr[1][2], bfr[1][3]);
            if (j + 1 < NT) { a0 = n0; a1 = n1; a2 = n2; a3 = n3; }
        }
    }
}

// ---------------------------------------------------------------------------
// Conv kernel: per (block, 128-filter half). Activity test folded in.
// 8 warps: wc=warp&3 (n32, SMSP-balanced), wr=warp>>2 (m-tiles 0-6 / 7-12).
// ---------------------------------------------------------------------------
__global__ void __launch_bounds__(256, 1)
conv_mma_kernel(const float* __restrict__ in, const float* __restrict__ mask,
                const float* __restrict__ bias, float* __restrict__ out) {
    int b = blockIdx.x;
    int fhalf = blockIdx.y;
    int nb = b >> 8, by = (b >> 4) & 15, bx = b & 15;
    int tid = threadIdx.x;
    int fbase = fhalf * 128;

    extern __shared__ char smem[];
    uint32_t sbase = smem_to_u32(smem);

    // ---- activity test (pooled mask mean > 0.5) ----
    {
        int ty = tid >> 4, tx = tid & 15;
        int h = by * OBS - 1 + ty;
        int w = bx * OBS - 1 + tx;
        float v = 0.f;
        if ((unsigned)h < HWD && (unsigned)w < HWD)
            v = mask[(nb * HWD + h) * HWD + w];
        double d = (double)v;
        #pragma unroll
        for (int o = 16; o > 0; o >>= 1)
            d += __shfl_down_sync(0xffffffffu, d, o);
        double* sred = (double*)(smem + REDOF);
        int* sflag = (int*)(smem + REDOF + 64);
        if ((tid & 31) == 0) sred[tid >> 5] = d;
        __syncthreads();
        if (tid == 0) {
            double s = 0.0;
            #pragma unroll
            for (int i = 0; i < 8; ++i) s += sred[i];
            *sflag = (s * (1.0 / 256.0) > 0.5) ? 1 : 0;
        }
        __syncthreads();
        if (!*sflag) {
            if (tid < 196) {
                int Y = by * OBS + tid / OBS, X = bx * OBS + tid % OBS;
                float4* o = (float4*)(out + (((size_t)nb * HWD + Y) * HWD + X) * FOUT + fbase);
                float4 z = make_float4(0.f, 0.f, 0.f, 0.f);
                #pragma unroll
                for (int i = 0; i < 32; ++i) o[i] = z;
            }
            return;
        }
    }

    int warp = tid >> 5, lane = tid & 31;
    int wc = warp & 3;          // n column-group (n32) -> SMSP-balanced
    int wr = warp >> 2;         // m row-group: tiles wr*7 .. (wr=1: 6 tiles)

    if (tid < 32) ((float4*)(smem + BIASOF))[tid] = ((const float4*)(bias + fbase))[tid];

    // per-lane A-row table (window pixel index per m-tile, pre-halo)
    int P0[7];
    {
        int mrow = (lane & 7) + ((lane >> 3) & 1) * 8;
        #pragma unroll
        for (int j = 0; j < 7; ++j) {
            int mt = wr * 7 + j;
            int m = mt * 16 + mrow;
            if (m > 195) m = 195;
            int py = m / 14, px = m - py * 14;
            P0[j] = (py + 1) * 16 + (px + 1);
        }
    }
    int acgl = (lane >> 4) & 1;
    int bnl  = ((lane >> 4) & 1) * 8 + (lane & 7);
    int bg0  = (lane >> 3) & 1;

    // B row bases (per warp, fixed all kernel)
    uint32_t brow[2], bp7[2];
    #pragma unroll
    for (int u = 0; u < 2; ++u) {
        int bn = wc * 32 + u * 16 + bnl;
        brow[u] = (uint32_t)bn * 128;
        bp7[u]  = (uint32_t)(bn & 7);
    }

    float acc[7][4][4];
    #pragma unroll
    for (int j = 0; j < 7; ++j)
        #pragma unroll
        for (int t = 0; t < 4; ++t)
            #pragma unroll
            for (int e = 0; e < 4; ++e) acc[j][t][e] = 0.f;

    const float* inb = in + (size_t)nb * HWD * HWD * CIN;
    int h0 = by * OBS - 1;
    int w0 = bx * OBS - 1;

    // window loader (fp32 LDG -> fp16 cvt -> STS into winbuf wb for chunk cc)
    auto load_window = [&](int cc, int wb) {
        int c0 = cc * 64;
        char* wdst = smem + WIN0 + wb * 32768;
        #pragma unroll
        for (int j = 0; j < 8; ++j) {
            int u = tid + j * 256;
            int p = u >> 3, g = u & 7;
            int y = p >> 4, x = p & 15;
            int gy = h0 + y, gx = w0 + x;
            float v[8];
            #pragma unroll
            for (int e = 0; e < 8; ++e) v[e] = 0.f;
            if ((unsigned)gy < HWD && (unsigned)gx < HWD) {
                const float* sp = inb + (((size_t)gy * HWD + gx) * CIN) + c0 + g * 8;
                float4 va = ((const float4*)sp)[0];
                float4 vb = ((const float4*)sp)[1];
                v[0] = va.x; v[1] = va.y; v[2] = va.z; v[3] = va.w;
                v[4] = vb.x; v[5] = vb.y; v[6] = vb.z; v[7] = vb.w;
            }
            union { __half hf[8]; uint4 u4; } H;
            #pragma unroll
            for (int e = 0; e < 8; ++e) H.hf[e] = __float2half_rn(v[e]);
            *(uint4*)(wdst + p * 128 + (((g ^ (p & 7))) << 4)) = H.u4;
        }
    };

    // B stage issuer: stage t -> buffer t%3 (12 cp.async of 16B per thread)
    auto issue_B = [&](int t) {
        int cct = t / 3, tbt = (t % 3) * 3;
        uint32_t bufb = sbase + BOFF + (uint32_t)(t % 3) * 49152;
        const __half* wsrc = g_W2 + tbt * 256 + cct * 64;
        #pragma unroll
        for (int j = 0; j < 12; ++j) {
            int u = tid + j * 256;
            int tl = u >> 10;
            int rem = u & 1023;
            int n = rem >> 3, g = rem & 7;
            const __half* src = wsrc + (size_t)(fbase + n) * KTOT + tl * 256 + g * 8;
            uint32_t dst = bufb + tl * 16384 + n * 128 + (((g ^ (n & 7))) << 4);
            CP_ASYNC16(dst, src);
        }
    };

    // prologue: B(0) in flight, window chunk 0 into winbuf 0
    issue_B(0);
    CP_COMMIT();
    load_window(0, 0);

    for (int s = 0; s < NSTG; ++s) {
        int cc = s / 3;
        int tb = (s % 3) * 3;

        if (s + 1 < NSTG) issue_B(s + 1);
        CP_COMMIT();
        CP_WAIT1();            // B(s) complete locally
        __syncthreads();       // publish B(s) + window/bias STS; compute(s-1) done

        // prefetch next chunk's window into the other winbuf
        if ((s % 3) == 2 && cc + 1 < 4) load_window(cc + 1, (cc + 1) & 1);

        uint32_t winb = sbase + WIN0 + (uint32_t)(cc & 1) * 32768;
        uint32_t bbuf = sbase + BOFF + (uint32_t)(s % 3) * 49152;

        #pragma unroll
        for (int tl = 0; tl < 3; ++tl) {
            int tap = tb + tl;
            int dy = tap / 3 - 1, dx = tap - (tap / 3) * 3 - 1;
            int doff = dy * 16 + dx;
            uint32_t btap = bbuf + tl * 16384;

            uint32_t arow[7], ap7[7];
            #pragma unroll
            for (int j = 0; j < 7; ++j) {
                int P = P0[j] + doff;
                arow[j] = (uint32_t)P * 128;
                ap7[j]  = (uint32_t)(P & 7);
            }
            if (wr == 0)
                compute_tap<7>(acc, winb, btap, arow, ap7, brow, bp7, acgl, bg0);
            else
                compute_tap<6>(acc, winb, btap, arow, ap7, brow, bp7, acgl, bg0);
        }
    }

    // ---- epilogue: bias + relu + store ----
    const float* sb = (const float*)(smem + BIASOF);
    #pragma unroll
    for (int j = 0; j < 7; ++j) {
        int mt = wr * 7 + j;
        if (mt < 13) {
            #pragma unroll
            for (int u = 0; u < 2; ++u) {
                #pragma unroll
                for (int hf = 0; hf < 2; ++hf) {
                    int nn = wc * 32 + u * 16 + hf * 8 + (lane & 3) * 2;
                    float bz0 = sb[nn], bz1 = sb[nn + 1];
                    #pragma unroll
                    for (int h2 = 0; h2 < 2; ++h2) {
                        int m = mt * 16 + (lane >> 2) + h2 * 8;
                        if (m < 196) {
                            int py = m / 14, px = m - py * 14;
                            float* o = out + (((size_t)nb * HWD + by * OBS + py) * HWD
                                              + bx * OBS + px) * FOUT + fbase + nn;
                            float2 v;
                            v.x = fmaxf(acc[j][u * 2 + hf][h2 * 2 + 0] + bz0, 0.f);
                            v.y = fmaxf(acc[j][u * 2 + hf][h2 * 2 + 1] + bz1, 0.f);
                            *(float2*)o = v;
                        }
                    }
                }
            }
        }
    }
}

extern "C" void kernel_launch(void* const* d_in, const int* in_sizes, int n_in,
                              void* d_out, int out_size) {
    (void)in_sizes; (void)n_in; (void)out_size;
    const float* in   = (const float*)d_in[0];   // (4,224,224,256)
    const float* mask = (const float*)d_in[1];   // (4,224,224,1)
    const float* wgt  = (const float*)d_in[2];   // (3,3,256,256)
    const float* bias = (const float*)d_in[3];   // (256,)
    float* out = (float*)d_out;

    cudaFuncSetAttribute(conv_mma_kernel,
                         cudaFuncAttributeMaxDynamicSharedMemorySize, SMEM_TOTAL);
    wprep_kernel<<<2304, 256>>>(wgt);
    dim3 grid(1024, 2);
    conv_mma_kernel<<<grid, 256, SMEM_TOTAL>>>(in, mask, bias, out);
}